// round 13
// baseline (speedup 1.0000x reference)
#include <cuda_runtime.h>
#include <cuda_bf16.h>
#include <cstdint>

#define B_    32
#define S_    2048
#define DH    512
#define E2    1024
#define INDIM 1536

// ---- scores GEMM tiling (bf16 mma.sync m16n8k16) ----
#define MTILE 128            // s rows per CTA
#define NTILE 128            // d cols per CTA
#define NCHUNKS (DH / NTILE) // 4 n-chunks: GEMM N-dim is DH (=512)
#define KSTG  64             // K elems per stage (128 B rows)
#define NSTG  (E2 / KSTG)    // 16 stages
#define TSTG  16384          // bytes per A-stage and per B-stage
#define A_OFF(p) ((p) * TSTG)
#define B_OFF(p) (3 * TSTG + (p) * TSTG)
#define GV_OFF   (6 * TSTG)
#define SMEM_TOTAL (GV_OFF + 2 * NTILE * 4)     // 99328 B -> 2 CTAs/SM

#define SCH   256            // context s-chunk
#define SWZ(off) ((off) ^ (((off) >> 3) & 0x70))

// k_small block roles
#define SM_G    B_                     // 32 blocks: g + zero + d_len
#define SM_W    512                    // w-conv blocks
#define SM_GRID (SM_G + SM_W)

// scratch (no cudaMalloc allowed)
__device__ int   d_len[B_];
__device__ float d_g[B_ * DH];
__device__ float d_scores[B_ * S_];
__device__ __nv_bfloat16 d_enc_bf[(size_t)B_ * S_ * E2];   // 128 MB
__device__ __nv_bfloat16 d_w_bf[DH * E2];                  // W_enc^T rows: [d][k]

__device__ __forceinline__ float fast_tanh(float x) {
    float y; asm("tanh.approx.f32 %0, %1;" : "=f"(y) : "f"(x)); return y;
}
__device__ __forceinline__ uint32_t pack_bf2(float lo, float hi) {
    uint32_t r; asm("cvt.rn.bf16x2.f32 %0, %1, %2;" : "=r"(r) : "f"(hi), "f"(lo)); return r;
}
__device__ __forceinline__ void cp16(uint32_t dst_smem, const void* src_gmem) {
    asm volatile("cp.async.cg.shared.global [%0], [%1], 16;\n" :: "r"(dst_smem), "l"(src_gmem));
}
__device__ __forceinline__ uint32_t smem_u32(const void* p) {
    uint32_t a;
    asm("{ .reg .u64 t; cvta.to.shared.u64 t, %1; cvt.u32.u64 %0, t; }" : "=r"(a) : "l"(p));
    return a;
}
__device__ __forceinline__ void ldsm4(uint32_t& r0, uint32_t& r1, uint32_t& r2, uint32_t& r3,
                                      uint32_t addr) {
    asm volatile("ldmatrix.sync.aligned.m8n8.x4.shared.b16 {%0,%1,%2,%3}, [%4];"
                 : "=r"(r0), "=r"(r1), "=r"(r2), "=r"(r3) : "r"(addr));
}
__device__ __forceinline__ void mma_bf16(float* c, const uint32_t* a, uint32_t b0, uint32_t b1) {
    asm volatile(
        "mma.sync.aligned.m16n8k16.row.col.f32.bf16.bf16.f32 "
        "{%0,%1,%2,%3}, {%4,%5,%6,%7}, {%8,%9}, {%0,%1,%2,%3};\n"
        : "+f"(c[0]), "+f"(c[1]), "+f"(c[2]), "+f"(c[3])
        : "r"(a[0]), "r"(a[1]), "r"(a[2]), "r"(a[3]), "r"(b0), "r"(b1));
}

// lengths dtype trap: jax without x64 silently yields int32 despite the int64
// annotation. First 128 bytes disambiguate: int64 layout has all odd 32-bit
// words zero (values <= 2048); int32 layout has them all >= 1.
__device__ __forceinline__ int read_len(const void* lens, int b) {
    const int* w = (const int*)lens;
    bool is64 = true;
#pragma unroll
    for (int i = 1; i < 32; i += 2)
        if (w[i] != 0) { is64 = false; break; }
    return is64 ? (int)((const long long*)lens)[b] : w[b];
}

// ---------------- Kernel 0: enc fp32 -> bf16 (length-masked, R6-proven shape) ----------------
__global__ void __launch_bounds__(256) k_conv_enc(const float* __restrict__ enc,
                                                  const void* __restrict__ lens) {
    int b = blockIdx.y;
    int s0 = blockIdx.x * 32;                 // 32 rows per block
    int len = read_len(lens, b);
    if ((s0 & ~127) >= len) return;           // whole 128-row score tile inactive
    int tid = threadIdx.x;                    // 256
    const float4* src = (const float4*)(enc + ((size_t)b * S_ + s0) * E2);
    uint2* dst = (uint2*)(d_enc_bf + ((size_t)b * S_ + s0) * E2);
#pragma unroll 8
    for (int i = tid; i < 32 * (E2 / 4); i += 256) {
        float4 v = src[i];
        dst[i] = make_uint2(pack_bf2(v.x, v.y), pack_bf2(v.z, v.w));
    }
}

// ---------------- Kernel 1: g-vector + W conversion + zeroing + d_len ----------------
// blocks [0,32):   d_len[b], g[b,:], zero d_scores row + out row
// blocks [32,544): convert attn_w[:,512:] -> d_w_bf (bf16)
__global__ void __launch_bounds__(256) k_small(const float* __restrict__ hidden,
                                               const float* __restrict__ attn_w,
                                               const float* __restrict__ attn_b,
                                               const void*  __restrict__ lens,
                                               float* __restrict__ out) {
    int bx = blockIdx.x, tid = threadIdx.x;

    if (bx >= SM_G) {
        int idx = (bx - SM_G) * 256 + tid;         // over DH*E2/4 float4s (131072)
        int d = idx >> 8;                          // 256 float4 per row
        int k4 = idx & 255;
        float4 v = *(const float4*)(attn_w + (size_t)d * INDIM + DH + k4 * 4);
        ((uint2*)d_w_bf)[d * 256 + k4] =
            make_uint2(pack_bf2(v.x, v.y), pack_bf2(v.z, v.w));
        return;
    }

    int b = bx;
    int len = read_len(lens, b);
    if (tid == 0) d_len[b] = len;
    float4 z4 = make_float4(0.f, 0.f, 0.f, 0.f);
    float4* zs = (float4*)(d_scores + b * S_);
    zs[tid] = z4; zs[tid + 256] = z4;
    ((float4*)(out + b * E2))[tid] = z4;

    __shared__ float hs[DH];
    hs[tid] = hidden[b * DH + tid];
    hs[tid + 256] = hidden[b * DH + tid + 256];
    __syncthreads();
#pragma unroll
    for (int r = 0; r < 2; r++) {
        int d = tid + r * 256;
        const float4* wr = (const float4*)(attn_w + (size_t)d * INDIM);
        float acc = attn_b[d];
#pragma unroll 8
        for (int j4 = 0; j4 < DH / 4; j4++) {
            float4 w = wr[j4];
            const float* h4 = &hs[j4 * 4];
            acc += w.x * h4[0] + w.y * h4[1] + w.z * h4[2] + w.w * h4[3];
        }
        d_g[b * DH + d] = acc;
    }
}

// ---------------- Kernel 2: bf16 HMMA scores ----------------
// grid (16 s-tiles, 4 n-chunks, 32 b), 256 threads = 8 warps (4 M x 2 N), 2 CTAs/SM.
// 3-stage cp.async pipeline, single __syncthreads per stage; next-stage load
// issued BEFORE the MMA block so DRAM latency overlaps tensor work.
__global__ void __launch_bounds__(256, 2) k_scores(const float* __restrict__ v_w) {
    extern __shared__ char smem[];
    int b   = blockIdx.z;
    int nch = blockIdx.y;
    int s0  = blockIdx.x * MTILE;
    if (s0 >= d_len[b]) return;

    int tid = threadIdx.x;
    int w = tid >> 5, lane = tid & 31;
    int wm = w & 3, wn = w >> 2;                   // 4 x 2 warp grid
    uint32_t sbase = smem_u32(smem);
    float* gs = (float*)(smem + GV_OFF);
    float* vs = gs + NTILE;
    if (tid < NTILE) {
        gs[tid] = d_g[b * DH + nch * NTILE + tid];
        vs[tid] = v_w[nch * NTILE + tid];
    }

    const char* Agp = (const char*)(d_enc_bf + ((size_t)b * S_ + s0) * E2);    // row 2048 B
    const char* Bgp = (const char*)(d_w_bf + (size_t)(nch * NTILE) * E2);      // row 2048 B

#define LOAD_STAGE(stg) do {                                                   \
        int _p = (stg) % 3;                                                    \
        _Pragma("unroll")                                                      \
        for (int _i = 0; _i < 4; _i++) {                                       \
            int _c = tid + _i * 256;                                           \
            int _r = _c >> 3, _cc = (_c & 7) * 16;                             \
            uint32_t _o = SWZ(_r * 128 + _cc);                                 \
            cp16(sbase + A_OFF(_p) + _o, Agp + (size_t)_r * 2048 + (stg) * 128 + _cc); \
            cp16(sbase + B_OFF(_p) + _o, Bgp + (size_t)_r * 2048 + (stg) * 128 + _cc); \
        }                                                                      \
        asm volatile("cp.async.commit_group;\n");                              \
    } while (0)

    // ldmatrix per-lane geometry
    int m2 = lane >> 3, r8 = lane & 7;
    int a_row = wm * 32 + r8 + (m2 & 1) * 8;
    int a_col = (m2 >> 1) * 16;                    // bytes
    int b_row = wn * 64 + r8 + (m2 >> 1) * 8;
    int b_col = (m2 & 1) * 16;

    float acc[2][8][4];
#pragma unroll
    for (int mt = 0; mt < 2; mt++)
#pragma unroll
        for (int nt = 0; nt < 8; nt++)
#pragma unroll
            for (int i = 0; i < 4; i++) acc[mt][nt][i] = 0.f;

    LOAD_STAGE(0);
    LOAD_STAGE(1);

    for (int kb = 0; kb < NSTG; kb++) {
        if (kb + 1 < NSTG) asm volatile("cp.async.wait_group 1;\n");
        else               asm volatile("cp.async.wait_group 0;\n");
        __syncthreads();   // stage kb visible; all warps past mma(kb-1) -> slot (kb+2)%3 free
        if (kb + 2 < NSTG) LOAD_STAGE(kb + 2);   // overlap loads with MMA below

        uint32_t SA = sbase + A_OFF(kb % 3);
        uint32_t SB = sbase + B_OFF(kb % 3);
#pragma unroll
        for (int ks = 0; ks < 4; ks++) {
            uint32_t a[2][4], bb[4][4];
#pragma unroll
            for (int mt = 0; mt < 2; mt++)
                ldsm4(a[mt][0], a[mt][1], a[mt][2], a[mt][3],
                      SA + SWZ((a_row + mt * 16) * 128 + ks * 32 + a_col));
#pragma unroll
            for (int j = 0; j < 4; j++)
                ldsm4(bb[j][0], bb[j][1], bb[j][2], bb[j][3],
                      SB + SWZ((b_row + j * 16) * 128 + ks * 32 + b_col));
#pragma unroll
            for (int mt = 0; mt < 2; mt++)
#pragma unroll
                for (int nt = 0; nt < 8; nt++) {
                    int j = nt >> 1, h = (nt & 1) * 2;
                    mma_bf16(acc[mt][nt], a[mt], bb[j][h], bb[j][h + 1]);
                }
        }
    }

    // epilogue: partial scores = sum_d v[d]*tanh(u+g)
    int g4 = lane >> 2, tg = lane & 3;
#pragma unroll
    for (int mt = 0; mt < 2; mt++) {
#pragma unroll
        for (int h = 0; h < 2; h++) {
            float sum = 0.f;
#pragma unroll
            for (int nt = 0; nt < 8; nt++) {
                int c = wn * 64 + nt * 8 + tg * 2;
                sum += vs[c]     * fast_tanh(acc[mt][nt][h * 2]     + gs[c]);
                sum += vs[c + 1] * fast_tanh(acc[mt][nt][h * 2 + 1] + gs[c + 1]);
            }
            sum += __shfl_xor_sync(0xffffffffu, sum, 1);
            sum += __shfl_xor_sync(0xffffffffu, sum, 2);
            if (tg == 0) {
                int row = wm * 32 + mt * 16 + g4 + h * 8;
                atomicAdd(&d_scores[b * S_ + s0 + row], sum);
            }
        }
    }
#undef LOAD_STAGE
}

// ---------------- Kernel 3: context with inline masked softmax ----------------
// grid (8 s-chunks, 32 b), 256 threads. Each block recomputes (M, Z) for its
// batch from d_scores (deterministic, identical across the batch's blocks),
// builds energies for its s-chunk, accumulates into out via atomics.
__global__ void __launch_bounds__(256) k_context(const float* __restrict__ enc,
                                                 float* __restrict__ out) {
    int b = blockIdx.y;
    int len = d_len[b];
    int s0 = blockIdx.x * SCH;
    if (s0 >= len) return;
    int tid = threadIdx.x;
    int ns = min(SCH, len - s0);
    const float* sc = d_scores + b * S_;

    __shared__ float red[8];
    __shared__ float sM, sZ;
    __shared__ float es[SCH];

    float m = -3.4e38f;
    for (int s = tid; s < len; s += 256) m = fmaxf(m, sc[s]);
#pragma unroll
    for (int o = 16; o; o >>= 1) m = fmaxf(m, __shfl_xor_sync(0xffffffffu, m, o));
    if ((tid & 31) == 0) red[tid >> 5] = m;
    __syncthreads();
    if (tid == 0) {
        float mm = red[0];
        for (int i = 1; i < 8; i++) mm = fmaxf(mm, red[i]);
        sM = mm;
    }
    __syncthreads();
    float M = sM;

    float z = 0.f;
    for (int s = tid; s < len; s += 256) z += __expf(sc[s] - M);
#pragma unroll
    for (int o = 16; o; o >>= 1) z += __shfl_xor_sync(0xffffffffu, z, o);
    if ((tid & 31) == 0) red[tid >> 5] = z;
    __syncthreads();
    if (tid == 0) {
        float zz = 0.f;
        for (int i = 0; i < 8; i++) zz += red[i];
        sZ = zz;
    }
    __syncthreads();
    float inv = 1.f / sZ;

    es[tid] = (tid < ns) ? __expf(sc[s0 + tid] - M) * inv : 0.f;
    __syncthreads();

    const float4* e4 = (const float4*)(enc + ((size_t)b * S_ + s0) * E2);
    float4 acc = make_float4(0.f, 0.f, 0.f, 0.f);
    int s = 0;
    for (; s + 4 <= ns; s += 4) {
        float w0 = es[s], w1 = es[s + 1], w2 = es[s + 2], w3 = es[s + 3];
        float4 v0 = e4[(size_t)(s + 0) * (E2 / 4) + tid];
        float4 v1 = e4[(size_t)(s + 1) * (E2 / 4) + tid];
        float4 v2 = e4[(size_t)(s + 2) * (E2 / 4) + tid];
        float4 v3 = e4[(size_t)(s + 3) * (E2 / 4) + tid];
        acc.x += w0 * v0.x + w1 * v1.x + w2 * v2.x + w3 * v3.x;
        acc.y += w0 * v0.y + w1 * v1.y + w2 * v2.y + w3 * v3.y;
        acc.z += w0 * v0.z + w1 * v1.z + w2 * v2.z + w3 * v3.z;
        acc.w += w0 * v0.w + w1 * v1.w + w2 * v2.w + w3 * v3.w;
    }
    for (; s < ns; s++) {
        float ww = es[s];
        float4 v = e4[(size_t)s * (E2 / 4) + tid];
        acc.x += ww * v.x; acc.y += ww * v.y; acc.z += ww * v.z; acc.w += ww * v.w;
    }
    float* o = out + b * E2 + tid * 4;
    atomicAdd(o + 0, acc.x);
    atomicAdd(o + 1, acc.y);
    atomicAdd(o + 2, acc.z);
    atomicAdd(o + 3, acc.w);
}

// ---------------- launch ----------------
extern "C" void kernel_launch(void* const* d_in, const int* in_sizes, int n_in,
                              void* d_out, int out_size) {
    const float* enc     = (const float*)d_in[0];
    const float* hidden  = (const float*)d_in[1];
    const void*  lengths = d_in[2];
    const float* attn_w  = (const float*)d_in[3];
    const float* attn_b  = (const float*)d_in[4];
    const float* v_w     = (const float*)d_in[5];
    float* out = (float*)d_out;

    k_conv_enc<<<dim3(S_ / 32, B_), 256>>>(enc, lengths);                    // 0
    k_small<<<SM_GRID, 256>>>(hidden, attn_w, attn_b, lengths, out);         // 1

    cudaFuncSetAttribute(k_scores, cudaFuncAttributeMaxDynamicSharedMemorySize, SMEM_TOTAL);
    k_scores<<<dim3(S_ / MTILE, NCHUNKS, B_), 256, SMEM_TOTAL>>>(v_w);       // 2

    k_context<<<dim3(S_ / SCH, B_), 256>>>(enc, out);                        // 3
}

// round 14
// speedup vs baseline: 1.2200x; 1.2200x over previous
#include <cuda_runtime.h>
#include <cuda_bf16.h>
#include <cstdint>

#define B_    32
#define S_    2048
#define DH    512
#define E2    1024
#define INDIM 1536

// ---- scores GEMM tiling (bf16 mma.sync m16n8k16) ----
#define MTILE 128            // s rows per CTA
#define NTILE 128            // d cols per CTA
#define NCHUNKS (DH / NTILE) // 4 n-chunks: GEMM N-dim is DH (=512)
#define KSTG  64             // K elems per stage (128 B rows)
#define NSTG  (E2 / KSTG)    // 16 stages
#define TSTG  16384          // bytes per A-stage and per B-stage
#define A_OFF(p) ((p) * TSTG)
#define B_OFF(p) (3 * TSTG + (p) * TSTG)
#define GV_OFF   (6 * TSTG)
#define SMEM_TOTAL (GV_OFF + 2 * NTILE * 4)     // 99328 B -> 2 CTAs/SM

#define SCH   64             // context s-chunk (small -> 1024 blocks -> occupancy)
#define SWZ(off) ((off) ^ (((off) >> 3) & 0x70))

// prep-kernel block roles
#define PREP_G     B_                    // 32 blocks: g + zero + d_len
#define PREP_W     512                   // w-conv blocks
#define PREP_ENC   (B_ * (S_ / 32))      // 2048 enc-conv blocks
#define PREP_GRID  (PREP_G + PREP_W + PREP_ENC)

// scratch (no cudaMalloc allowed)
__device__ int   d_len[B_];
__device__ float d_g[B_ * DH];
__device__ float d_scores[B_ * S_];
__device__ __nv_bfloat16 d_enc_bf[(size_t)B_ * S_ * E2];   // 128 MB
__device__ __nv_bfloat16 d_w_bf[DH * E2];                  // W_enc^T rows: [d][k]

__device__ __forceinline__ float fast_tanh(float x) {
    float y; asm("tanh.approx.f32 %0, %1;" : "=f"(y) : "f"(x)); return y;
}
__device__ __forceinline__ uint32_t pack_bf2(float lo, float hi) {
    uint32_t r; asm("cvt.rn.bf16x2.f32 %0, %1, %2;" : "=r"(r) : "f"(hi), "f"(lo)); return r;
}
__device__ __forceinline__ void cp16(uint32_t dst_smem, const void* src_gmem) {
    asm volatile("cp.async.cg.shared.global [%0], [%1], 16;\n" :: "r"(dst_smem), "l"(src_gmem));
}
__device__ __forceinline__ uint32_t smem_u32(const void* p) {
    uint32_t a;
    asm("{ .reg .u64 t; cvta.to.shared.u64 t, %1; cvt.u32.u64 %0, t; }" : "=r"(a) : "l"(p));
    return a;
}
__device__ __forceinline__ void ldsm4(uint32_t& r0, uint32_t& r1, uint32_t& r2, uint32_t& r3,
                                      uint32_t addr) {
    asm volatile("ldmatrix.sync.aligned.m8n8.x4.shared.b16 {%0,%1,%2,%3}, [%4];"
                 : "=r"(r0), "=r"(r1), "=r"(r2), "=r"(r3) : "r"(addr));
}
__device__ __forceinline__ void mma_bf16(float* c, const uint32_t* a, uint32_t b0, uint32_t b1) {
    asm volatile(
        "mma.sync.aligned.m16n8k16.row.col.f32.bf16.bf16.f32 "
        "{%0,%1,%2,%3}, {%4,%5,%6,%7}, {%8,%9}, {%0,%1,%2,%3};\n"
        : "+f"(c[0]), "+f"(c[1]), "+f"(c[2]), "+f"(c[3])
        : "r"(a[0]), "r"(a[1]), "r"(a[2]), "r"(a[3]), "r"(b0), "r"(b1));
}

// lengths dtype trap: jax without x64 silently yields int32 despite the int64
// annotation. First 128 bytes disambiguate: int64 layout has all odd 32-bit
// words zero (values <= 2048); int32 layout has them all >= 1.
__device__ __forceinline__ int read_len(const void* lens, int b) {
    const int* w = (const int*)lens;
    bool is64 = true;
#pragma unroll
    for (int i = 1; i < 32; i += 2)
        if (w[i] != 0) { is64 = false; break; }
    return is64 ? (int)((const long long*)lens)[b] : w[b];
}

// ---------------- Kernel 0 (merged prep) ----------------
// blocks [0,32):      d_len[b], g[b,:], zero d_scores row + out row
// blocks [32,544):    convert attn_w[:,512:] -> d_w_bf (bf16)
// blocks [544,2592):  convert enc fp32 -> bf16 (length-masked, 32 rows/block)
__global__ void __launch_bounds__(256) k_prep(const float* __restrict__ hidden,
                                              const float* __restrict__ attn_w,
                                              const float* __restrict__ attn_b,
                                              const float* __restrict__ enc,
                                              const void*  __restrict__ lens,
                                              float* __restrict__ out) {
    int bx = blockIdx.x, tid = threadIdx.x;

    if (bx < PREP_G) {
        int b = bx;
        int len = read_len(lens, b);
        if (tid == 0) d_len[b] = len;
        float4 z4 = make_float4(0.f, 0.f, 0.f, 0.f);
        float4* zs = (float4*)(d_scores + b * S_);
        zs[tid] = z4; zs[tid + 256] = z4;
        ((float4*)(out + b * E2))[tid] = z4;

        __shared__ float hs[DH];
        hs[tid] = hidden[b * DH + tid];
        hs[tid + 256] = hidden[b * DH + tid + 256];
        __syncthreads();
#pragma unroll
        for (int r = 0; r < 2; r++) {
            int d = tid + r * 256;
            const float4* wr = (const float4*)(attn_w + (size_t)d * INDIM);
            float acc = attn_b[d];
#pragma unroll 4
            for (int j4 = 0; j4 < DH / 4; j4++) {
                float4 w = wr[j4];
                const float* h4 = &hs[j4 * 4];
                acc += w.x * h4[0] + w.y * h4[1] + w.z * h4[2] + w.w * h4[3];
            }
            d_g[b * DH + d] = acc;
        }
        return;
    }

    if (bx < PREP_G + PREP_W) {
        int idx = (bx - PREP_G) * 256 + tid;       // over DH*E2/4 float4s (131072)
        int d = idx >> 8;                          // 256 float4 per row
        int k4 = idx & 255;
        float4 v = *(const float4*)(attn_w + (size_t)d * INDIM + DH + k4 * 4);
        ((uint2*)d_w_bf)[d * 256 + k4] =
            make_uint2(pack_bf2(v.x, v.y), pack_bf2(v.z, v.w));
        return;
    }

    int bx2 = bx - (PREP_G + PREP_W);              // [0,2048)
    int b  = bx2 >> 6;                             // 64 blocks per batch
    int s0 = (bx2 & 63) * 32;
    int len = read_len(lens, b);                   // inline (no intra-kernel ordering)
    if ((s0 & ~127) >= len) return;                // whole 128-row score tile inactive
    const float4* src = (const float4*)(enc + ((size_t)b * S_ + s0) * E2);
    uint2* dst = (uint2*)(d_enc_bf + ((size_t)b * S_ + s0) * E2);
#pragma unroll 8
    for (int i = tid; i < 32 * (E2 / 4); i += 256) {
        float4 v = src[i];
        dst[i] = make_uint2(pack_bf2(v.x, v.y), pack_bf2(v.z, v.w));
    }
}

// ---------------- Kernel 1: bf16 HMMA scores ----------------
// grid (16 s-tiles, 4 n-chunks, 32 b), 256 threads = 8 warps (4 M x 2 N), 2 CTAs/SM.
// 3-stage cp.async pipeline, single __syncthreads per stage; next-stage load
// issued BEFORE the MMA block so DRAM latency overlaps tensor work.
__global__ void __launch_bounds__(256, 2) k_scores(const float* __restrict__ v_w) {
    extern __shared__ char smem[];
    int b   = blockIdx.z;
    int nch = blockIdx.y;
    int s0  = blockIdx.x * MTILE;
    if (s0 >= d_len[b]) return;

    int tid = threadIdx.x;
    int w = tid >> 5, lane = tid & 31;
    int wm = w & 3, wn = w >> 2;                   // 4 x 2 warp grid
    uint32_t sbase = smem_u32(smem);
    float* gs = (float*)(smem + GV_OFF);
    float* vs = gs + NTILE;
    if (tid < NTILE) {
        gs[tid] = d_g[b * DH + nch * NTILE + tid];
        vs[tid] = v_w[nch * NTILE + tid];
    }

    const char* Agp = (const char*)(d_enc_bf + ((size_t)b * S_ + s0) * E2);    // row 2048 B
    const char* Bgp = (const char*)(d_w_bf + (size_t)(nch * NTILE) * E2);      // row 2048 B

#define LOAD_STAGE(stg) do {                                                   \
        int _p = (stg) % 3;                                                    \
        _Pragma("unroll")                                                      \
        for (int _i = 0; _i < 4; _i++) {                                       \
            int _c = tid + _i * 256;                                           \
            int _r = _c >> 3, _cc = (_c & 7) * 16;                             \
            uint32_t _o = SWZ(_r * 128 + _cc);                                 \
            cp16(sbase + A_OFF(_p) + _o, Agp + (size_t)_r * 2048 + (stg) * 128 + _cc); \
            cp16(sbase + B_OFF(_p) + _o, Bgp + (size_t)_r * 2048 + (stg) * 128 + _cc); \
        }                                                                      \
        asm volatile("cp.async.commit_group;\n");                              \
    } while (0)

    // ldmatrix per-lane geometry
    int m2 = lane >> 3, r8 = lane & 7;
    int a_row = wm * 32 + r8 + (m2 & 1) * 8;
    int a_col = (m2 >> 1) * 16;                    // bytes
    int b_row = wn * 64 + r8 + (m2 >> 1) * 8;
    int b_col = (m2 & 1) * 16;

    float acc[2][8][4];
#pragma unroll
    for (int mt = 0; mt < 2; mt++)
#pragma unroll
        for (int nt = 0; nt < 8; nt++)
#pragma unroll
            for (int i = 0; i < 4; i++) acc[mt][nt][i] = 0.f;

    LOAD_STAGE(0);
    LOAD_STAGE(1);

    for (int kb = 0; kb < NSTG; kb++) {
        if (kb + 1 < NSTG) asm volatile("cp.async.wait_group 1;\n");
        else               asm volatile("cp.async.wait_group 0;\n");
        __syncthreads();   // stage kb visible; all warps past mma(kb-1) -> slot (kb+2)%3 free
        if (kb + 2 < NSTG) LOAD_STAGE(kb + 2);   // overlap loads with MMA below

        uint32_t SA = sbase + A_OFF(kb % 3);
        uint32_t SB = sbase + B_OFF(kb % 3);
#pragma unroll
        for (int ks = 0; ks < 4; ks++) {
            uint32_t a[2][4], bb[4][4];
#pragma unroll
            for (int mt = 0; mt < 2; mt++)
                ldsm4(a[mt][0], a[mt][1], a[mt][2], a[mt][3],
                      SA + SWZ((a_row + mt * 16) * 128 + ks * 32 + a_col));
#pragma unroll
            for (int j = 0; j < 4; j++)
                ldsm4(bb[j][0], bb[j][1], bb[j][2], bb[j][3],
                      SB + SWZ((b_row + j * 16) * 128 + ks * 32 + b_col));
#pragma unroll
            for (int mt = 0; mt < 2; mt++)
#pragma unroll
                for (int nt = 0; nt < 8; nt++) {
                    int j = nt >> 1, h = (nt & 1) * 2;
                    mma_bf16(acc[mt][nt], a[mt], bb[j][h], bb[j][h + 1]);
                }
        }
    }

    // epilogue: partial scores = sum_d v[d]*tanh(u+g)
    int g4 = lane >> 2, tg = lane & 3;
#pragma unroll
    for (int mt = 0; mt < 2; mt++) {
#pragma unroll
        for (int h = 0; h < 2; h++) {
            float sum = 0.f;
#pragma unroll
            for (int nt = 0; nt < 8; nt++) {
                int c = wn * 64 + nt * 8 + tg * 2;
                sum += vs[c]     * fast_tanh(acc[mt][nt][h * 2]     + gs[c]);
                sum += vs[c + 1] * fast_tanh(acc[mt][nt][h * 2 + 1] + gs[c + 1]);
            }
            sum += __shfl_xor_sync(0xffffffffu, sum, 1);
            sum += __shfl_xor_sync(0xffffffffu, sum, 2);
            if (tg == 0) {
                int row = wm * 32 + mt * 16 + g4 + h * 8;
                atomicAdd(&d_scores[b * S_ + s0 + row], sum);
            }
        }
    }
#undef LOAD_STAGE
}

// ---------------- Kernel 2: context with inline masked softmax ----------------
// grid (32 s-chunks of 64, 32 b) = 1024 blocks, 256 threads. Each block
// recomputes (M, Z) for its batch from d_scores (L2-resident, deterministic,
// identical across the batch's blocks), then accumulates its 64-row chunk.
__global__ void __launch_bounds__(256) k_context(const float* __restrict__ enc,
                                                 float* __restrict__ out) {
    int b = blockIdx.y;
    int len = d_len[b];
    int s0 = blockIdx.x * SCH;
    if (s0 >= len) return;
    int tid = threadIdx.x;
    int ns = min(SCH, len - s0);
    const float* sc = d_scores + b * S_;

    __shared__ float red[8];
    __shared__ float sM, sZ;
    __shared__ float es[SCH];

    float m = -3.4e38f;
    for (int s = tid; s < len; s += 256) m = fmaxf(m, sc[s]);
#pragma unroll
    for (int o = 16; o; o >>= 1) m = fmaxf(m, __shfl_xor_sync(0xffffffffu, m, o));
    if ((tid & 31) == 0) red[tid >> 5] = m;
    __syncthreads();
    if (tid == 0) {
        float mm = red[0];
        for (int i = 1; i < 8; i++) mm = fmaxf(mm, red[i]);
        sM = mm;
    }
    __syncthreads();
    float M = sM;

    float z = 0.f;
    for (int s = tid; s < len; s += 256) z += __expf(sc[s] - M);
#pragma unroll
    for (int o = 16; o; o >>= 1) z += __shfl_xor_sync(0xffffffffu, z, o);
    if ((tid & 31) == 0) red[tid >> 5] = z;
    __syncthreads();
    if (tid == 0) {
        float zz = 0.f;
        for (int i = 0; i < 8; i++) zz += red[i];
        sZ = zz;
    }
    __syncthreads();
    float inv = 1.f / sZ;

    if (tid < SCH) es[tid] = (tid < ns) ? __expf(sc[s0 + tid] - M) * inv : 0.f;
    __syncthreads();

    const float4* e4 = (const float4*)(enc + ((size_t)b * S_ + s0) * E2);
    float4 acc = make_float4(0.f, 0.f, 0.f, 0.f);
    int s = 0;
    for (; s + 4 <= ns; s += 4) {
        float w0 = es[s], w1 = es[s + 1], w2 = es[s + 2], w3 = es[s + 3];
        float4 v0 = e4[(size_t)(s + 0) * (E2 / 4) + tid];
        float4 v1 = e4[(size_t)(s + 1) * (E2 / 4) + tid];
        float4 v2 = e4[(size_t)(s + 2) * (E2 / 4) + tid];
        float4 v3 = e4[(size_t)(s + 3) * (E2 / 4) + tid];
        acc.x += w0 * v0.x + w1 * v1.x + w2 * v2.x + w3 * v3.x;
        acc.y += w0 * v0.y + w1 * v1.y + w2 * v2.y + w3 * v3.y;
        acc.z += w0 * v0.z + w1 * v1.z + w2 * v2.z + w3 * v3.z;
        acc.w += w0 * v0.w + w1 * v1.w + w2 * v2.w + w3 * v3.w;
    }
    for (; s < ns; s++) {
        float ww = es[s];
        float4 v = e4[(size_t)s * (E2 / 4) + tid];
        acc.x += ww * v.x; acc.y += ww * v.y; acc.z += ww * v.z; acc.w += ww * v.w;
    }
    float* o = out + b * E2 + tid * 4;
    atomicAdd(o + 0, acc.x);
    atomicAdd(o + 1, acc.y);
    atomicAdd(o + 2, acc.z);
    atomicAdd(o + 3, acc.w);
}

// ---------------- launch ----------------
extern "C" void kernel_launch(void* const* d_in, const int* in_sizes, int n_in,
                              void* d_out, int out_size) {
    const float* enc     = (const float*)d_in[0];
    const float* hidden  = (const float*)d_in[1];
    const void*  lengths = d_in[2];
    const float* attn_w  = (const float*)d_in[3];
    const float* attn_b  = (const float*)d_in[4];
    const float* v_w     = (const float*)d_in[5];
    float* out = (float*)d_out;

    k_prep<<<PREP_GRID, 256>>>(hidden, attn_w, attn_b, enc, lengths, out);   // 0

    cudaFuncSetAttribute(k_scores, cudaFuncAttributeMaxDynamicSharedMemorySize, SMEM_TOTAL);
    k_scores<<<dim3(S_ / MTILE, NCHUNKS, B_), 256, SMEM_TOTAL>>>(v_w);       // 1

    k_context<<<dim3(S_ / SCH, B_), 256>>>(enc, out);                        // 2
}

// round 15
// speedup vs baseline: 1.4282x; 1.1706x over previous
#include <cuda_runtime.h>
#include <cuda_bf16.h>
#include <cstdint>

#define B_    32
#define S_    2048
#define DH    512
#define E2    1024
#define INDIM 1536

// ---- scores GEMM tiling (bf16 mma.sync m16n8k16) ----
#define MTILE 128            // s rows per CTA
#define NTILE 128            // d cols per CTA
#define NCHUNKS (DH / NTILE) // 4 n-chunks: GEMM N-dim is DH (=512)
#define KSTG  64             // K elems per stage (128 B rows)
#define NSTG  (E2 / KSTG)    // 16 stages
#define TSTG  16384          // bytes per A-stage and per B-stage
#define A_OFF(p) ((p) * TSTG)
#define B_OFF(p) (3 * TSTG + (p) * TSTG)
#define GV_OFF   (6 * TSTG)
#define SMEM_TOTAL (GV_OFF + 2 * NTILE * 4)     // 99328 B -> 2 CTAs/SM

#define SCH   64             // context s-chunk (1024 blocks -> occupancy)
#define SWZ(off) ((off) ^ (((off) >> 3) & 0x70))

// prep-kernel block roles
#define PREP_G     256                   // 8 blocks per batch: g-GEMV (64 d each)
#define PREP_W     512                   // w-conv blocks (first 32 also zero scores/out)
#define PREP_ENC   (B_ * (S_ / 32))      // 2048 enc-conv blocks
#define PREP_GRID  (PREP_G + PREP_W + PREP_ENC)

// scratch (no cudaMalloc allowed)
__device__ int   d_len[B_];
__device__ float d_g[B_ * DH];
__device__ float d_scores[B_ * S_];
__device__ __nv_bfloat16 d_enc_bf[(size_t)B_ * S_ * E2];   // 128 MB
__device__ __nv_bfloat16 d_w_bf[DH * E2];                  // W_enc^T rows: [d][k]

__device__ __forceinline__ float fast_tanh(float x) {
    float y; asm("tanh.approx.f32 %0, %1;" : "=f"(y) : "f"(x)); return y;
}
__device__ __forceinline__ uint32_t pack_bf2(float lo, float hi) {
    uint32_t r; asm("cvt.rn.bf16x2.f32 %0, %1, %2;" : "=r"(r) : "f"(hi), "f"(lo)); return r;
}
__device__ __forceinline__ void cp16(uint32_t dst_smem, const void* src_gmem) {
    asm volatile("cp.async.cg.shared.global [%0], [%1], 16;\n" :: "r"(dst_smem), "l"(src_gmem));
}
__device__ __forceinline__ uint32_t smem_u32(const void* p) {
    uint32_t a;
    asm("{ .reg .u64 t; cvta.to.shared.u64 t, %1; cvt.u32.u64 %0, t; }" : "=r"(a) : "l"(p));
    return a;
}
__device__ __forceinline__ void ldsm4(uint32_t& r0, uint32_t& r1, uint32_t& r2, uint32_t& r3,
                                      uint32_t addr) {
    asm volatile("ldmatrix.sync.aligned.m8n8.x4.shared.b16 {%0,%1,%2,%3}, [%4];"
                 : "=r"(r0), "=r"(r1), "=r"(r2), "=r"(r3) : "r"(addr));
}
__device__ __forceinline__ void mma_bf16(float* c, const uint32_t* a, uint32_t b0, uint32_t b1) {
    asm volatile(
        "mma.sync.aligned.m16n8k16.row.col.f32.bf16.bf16.f32 "
        "{%0,%1,%2,%3}, {%4,%5,%6,%7}, {%8,%9}, {%0,%1,%2,%3};\n"
        : "+f"(c[0]), "+f"(c[1]), "+f"(c[2]), "+f"(c[3])
        : "r"(a[0]), "r"(a[1]), "r"(a[2]), "r"(a[3]), "r"(b0), "r"(b1));
}

// lengths dtype trap: jax without x64 silently yields int32 despite the int64
// annotation. First 128 bytes disambiguate: int64 layout has all odd 32-bit
// words zero (values <= 2048); int32 layout has them all >= 1.
__device__ __forceinline__ int read_len(const void* lens, int b) {
    const int* w = (const int*)lens;
    bool is64 = true;
#pragma unroll
    for (int i = 1; i < 32; i += 2)
        if (w[i] != 0) { is64 = false; break; }
    return is64 ? (int)((const long long*)lens)[b] : w[b];
}

// ---------------- Kernel 0 (merged prep) ----------------
// blocks [0,256):     g-GEMV: block (b, dg) computes g[b, dg*64 .. dg*64+64)
//                     4 threads per d, 32 contiguous float4 loads each (MLP-8).
//                     dg==0 block also writes d_len[b].
// blocks [256,768):   convert attn_w[:,512:] -> d_w_bf; first 32 also zero
//                     d_scores row + out row for batch (bx-256).
// blocks [768,2816):  convert enc fp32 -> bf16 (length-masked, 32 rows/block)
__global__ void __launch_bounds__(256) k_prep(const float* __restrict__ hidden,
                                              const float* __restrict__ attn_w,
                                              const float* __restrict__ attn_b,
                                              const float* __restrict__ enc,
                                              const void*  __restrict__ lens,
                                              float* __restrict__ out) {
    int bx = blockIdx.x, tid = threadIdx.x;

    if (bx < PREP_G) {
        int b  = bx >> 3;
        int dg = bx & 7;
        if (dg == 0 && tid == 0) d_len[b] = read_len(lens, b);

        __shared__ float hs[DH];
        hs[tid] = hidden[b * DH + tid];
        hs[tid + 256] = hidden[b * DH + tid + 256];
        __syncthreads();

        int d    = dg * 64 + (tid >> 2);
        int part = tid & 3;                        // quarter of the j-range
        const float4* wr = (const float4*)(attn_w + (size_t)d * INDIM) + part * 32;
        const float*  h4 = hs + part * 128;
        float acc = 0.f;
#pragma unroll 8
        for (int j4 = 0; j4 < 32; j4++) {
            float4 w = wr[j4];
            acc += w.x * h4[j4 * 4] + w.y * h4[j4 * 4 + 1]
                 + w.z * h4[j4 * 4 + 2] + w.w * h4[j4 * 4 + 3];
        }
        acc += __shfl_xor_sync(0xffffffffu, acc, 1);
        acc += __shfl_xor_sync(0xffffffffu, acc, 2);
        if (part == 0) d_g[b * DH + d] = acc + attn_b[d];
        return;
    }

    if (bx < PREP_G + PREP_W) {
        int wb = bx - PREP_G;
        if (wb < B_) {
            // zero scores row + out row for batch wb
            float4 z4 = make_float4(0.f, 0.f, 0.f, 0.f);
            float4* zs = (float4*)(d_scores + wb * S_);
            zs[tid] = z4; zs[tid + 256] = z4;
            ((float4*)(out + wb * E2))[tid] = z4;
        }
        int idx = wb * 256 + tid;                  // over DH*E2/4 float4s (131072)
        int d = idx >> 8;                          // 256 float4 per row
        int k4 = idx & 255;
        float4 v = *(const float4*)(attn_w + (size_t)d * INDIM + DH + k4 * 4);
        ((uint2*)d_w_bf)[d * 256 + k4] =
            make_uint2(pack_bf2(v.x, v.y), pack_bf2(v.z, v.w));
        return;
    }

    int bx2 = bx - (PREP_G + PREP_W);              // [0,2048)
    int b  = bx2 >> 6;                             // 64 blocks per batch
    int s0 = (bx2 & 63) * 32;
    int len = read_len(lens, b);                   // inline (no intra-kernel ordering)
    if ((s0 & ~127) >= len) return;                // whole 128-row score tile inactive
    const float4* src = (const float4*)(enc + ((size_t)b * S_ + s0) * E2);
    uint2* dst = (uint2*)(d_enc_bf + ((size_t)b * S_ + s0) * E2);
#pragma unroll 8
    for (int i = tid; i < 32 * (E2 / 4); i += 256) {
        float4 v = src[i];
        dst[i] = make_uint2(pack_bf2(v.x, v.y), pack_bf2(v.z, v.w));
    }
}

// ---------------- Kernel 1: bf16 HMMA scores ----------------
// grid (16 s-tiles, 4 n-chunks, 32 b), 256 threads = 8 warps (4 M x 2 N), 2 CTAs/SM.
// 3-stage cp.async pipeline, single __syncthreads per stage; next-stage load
// issued BEFORE the MMA block so DRAM latency overlaps tensor work.
__global__ void __launch_bounds__(256, 2) k_scores(const float* __restrict__ v_w) {
    extern __shared__ char smem[];
    int b   = blockIdx.z;
    int nch = blockIdx.y;
    int s0  = blockIdx.x * MTILE;
    if (s0 >= d_len[b]) return;

    int tid = threadIdx.x;
    int w = tid >> 5, lane = tid & 31;
    int wm = w & 3, wn = w >> 2;                   // 4 x 2 warp grid
    uint32_t sbase = smem_u32(smem);
    float* gs = (float*)(smem + GV_OFF);
    float* vs = gs + NTILE;
    if (tid < NTILE) {
        gs[tid] = d_g[b * DH + nch * NTILE + tid];
        vs[tid] = v_w[nch * NTILE + tid];
    }

    const char* Agp = (const char*)(d_enc_bf + ((size_t)b * S_ + s0) * E2);    // row 2048 B
    const char* Bgp = (const char*)(d_w_bf + (size_t)(nch * NTILE) * E2);      // row 2048 B

#define LOAD_STAGE(stg) do {                                                   \
        int _p = (stg) % 3;                                                    \
        _Pragma("unroll")                                                      \
        for (int _i = 0; _i < 4; _i++) {                                       \
            int _c = tid + _i * 256;                                           \
            int _r = _c >> 3, _cc = (_c & 7) * 16;                             \
            uint32_t _o = SWZ(_r * 128 + _cc);                                 \
            cp16(sbase + A_OFF(_p) + _o, Agp + (size_t)_r * 2048 + (stg) * 128 + _cc); \
            cp16(sbase + B_OFF(_p) + _o, Bgp + (size_t)_r * 2048 + (stg) * 128 + _cc); \
        }                                                                      \
        asm volatile("cp.async.commit_group;\n");                              \
    } while (0)

    // ldmatrix per-lane geometry
    int m2 = lane >> 3, r8 = lane & 7;
    int a_row = wm * 32 + r8 + (m2 & 1) * 8;
    int a_col = (m2 >> 1) * 16;                    // bytes
    int b_row = wn * 64 + r8 + (m2 >> 1) * 8;
    int b_col = (m2 & 1) * 16;

    float acc[2][8][4];
#pragma unroll
    for (int mt = 0; mt < 2; mt++)
#pragma unroll
        for (int nt = 0; nt < 8; nt++)
#pragma unroll
            for (int i = 0; i < 4; i++) acc[mt][nt][i] = 0.f;

    LOAD_STAGE(0);
    LOAD_STAGE(1);

    for (int kb = 0; kb < NSTG; kb++) {
        if (kb + 1 < NSTG) asm volatile("cp.async.wait_group 1;\n");
        else               asm volatile("cp.async.wait_group 0;\n");
        __syncthreads();   // stage kb visible; all warps past mma(kb-1) -> slot (kb+2)%3 free
        if (kb + 2 < NSTG) LOAD_STAGE(kb + 2);   // overlap loads with MMA below

        uint32_t SA = sbase + A_OFF(kb % 3);
        uint32_t SB = sbase + B_OFF(kb % 3);
#pragma unroll
        for (int ks = 0; ks < 4; ks++) {
            uint32_t a[2][4], bb[4][4];
#pragma unroll
            for (int mt = 0; mt < 2; mt++)
                ldsm4(a[mt][0], a[mt][1], a[mt][2], a[mt][3],
                      SA + SWZ((a_row + mt * 16) * 128 + ks * 32 + a_col));
#pragma unroll
            for (int j = 0; j < 4; j++)
                ldsm4(bb[j][0], bb[j][1], bb[j][2], bb[j][3],
                      SB + SWZ((b_row + j * 16) * 128 + ks * 32 + b_col));
#pragma unroll
            for (int mt = 0; mt < 2; mt++)
#pragma unroll
                for (int nt = 0; nt < 8; nt++) {
                    int j = nt >> 1, h = (nt & 1) * 2;
                    mma_bf16(acc[mt][nt], a[mt], bb[j][h], bb[j][h + 1]);
                }
        }
    }

    // epilogue: partial scores = sum_d v[d]*tanh(u+g)
    int g4 = lane >> 2, tg = lane & 3;
#pragma unroll
    for (int mt = 0; mt < 2; mt++) {
#pragma unroll
        for (int h = 0; h < 2; h++) {
            float sum = 0.f;
#pragma unroll
            for (int nt = 0; nt < 8; nt++) {
                int c = wn * 64 + nt * 8 + tg * 2;
                sum += vs[c]     * fast_tanh(acc[mt][nt][h * 2]     + gs[c]);
                sum += vs[c + 1] * fast_tanh(acc[mt][nt][h * 2 + 1] + gs[c + 1]);
            }
            sum += __shfl_xor_sync(0xffffffffu, sum, 1);
            sum += __shfl_xor_sync(0xffffffffu, sum, 2);
            if (tg == 0) {
                int row = wm * 32 + mt * 16 + g4 + h * 8;
                atomicAdd(&d_scores[b * S_ + s0 + row], sum);
            }
        }
    }
#undef LOAD_STAGE
}

// ---------------- Kernel 2: context with inline masked softmax ----------------
// grid (32 s-chunks of 64, 32 b) = 1024 blocks, 256 threads. Each block
// recomputes (M, Z) for its batch from d_scores (L2-resident, deterministic,
// identical across the batch's blocks), then accumulates its 64-row chunk.
__global__ void __launch_bounds__(256) k_context(const float* __restrict__ enc,
                                                 float* __restrict__ out) {
    int b = blockIdx.y;
    int len = d_len[b];
    int s0 = blockIdx.x * SCH;
    if (s0 >= len) return;
    int tid = threadIdx.x;
    int ns = min(SCH, len - s0);
    const float* sc = d_scores + b * S_;

    __shared__ float red[8];
    __shared__ float sM, sZ;
    __shared__ float es[SCH];

    float m = -3.4e38f;
    for (int s = tid; s < len; s += 256) m = fmaxf(m, sc[s]);
#pragma unroll
    for (int o = 16; o; o >>= 1) m = fmaxf(m, __shfl_xor_sync(0xffffffffu, m, o));
    if ((tid & 31) == 0) red[tid >> 5] = m;
    __syncthreads();
    if (tid == 0) {
        float mm = red[0];
        for (int i = 1; i < 8; i++) mm = fmaxf(mm, red[i]);
        sM = mm;
    }
    __syncthreads();
    float M = sM;

    float z = 0.f;
    for (int s = tid; s < len; s += 256) z += __expf(sc[s] - M);
#pragma unroll
    for (int o = 16; o; o >>= 1) z += __shfl_xor_sync(0xffffffffu, z, o);
    if ((tid & 31) == 0) red[tid >> 5] = z;
    __syncthreads();
    if (tid == 0) {
        float zz = 0.f;
        for (int i = 0; i < 8; i++) zz += red[i];
        sZ = zz;
    }
    __syncthreads();
    float inv = 1.f / sZ;

    if (tid < SCH) es[tid] = (tid < ns) ? __expf(sc[s0 + tid] - M) * inv : 0.f;
    __syncthreads();

    const float4* e4 = (const float4*)(enc + ((size_t)b * S_ + s0) * E2);
    float4 acc = make_float4(0.f, 0.f, 0.f, 0.f);
    int s = 0;
    for (; s + 4 <= ns; s += 4) {
        float w0 = es[s], w1 = es[s + 1], w2 = es[s + 2], w3 = es[s + 3];
        float4 v0 = e4[(size_t)(s + 0) * (E2 / 4) + tid];
        float4 v1 = e4[(size_t)(s + 1) * (E2 / 4) + tid];
        float4 v2 = e4[(size_t)(s + 2) * (E2 / 4) + tid];
        float4 v3 = e4[(size_t)(s + 3) * (E2 / 4) + tid];
        acc.x += w0 * v0.x + w1 * v1.x + w2 * v2.x + w3 * v3.x;
        acc.y += w0 * v0.y + w1 * v1.y + w2 * v2.y + w3 * v3.y;
        acc.z += w0 * v0.z + w1 * v1.z + w2 * v2.z + w3 * v3.z;
        acc.w += w0 * v0.w + w1 * v1.w + w2 * v2.w + w3 * v3.w;
    }
    for (; s < ns; s++) {
        float ww = es[s];
        float4 v = e4[(size_t)s * (E2 / 4) + tid];
        acc.x += ww * v.x; acc.y += ww * v.y; acc.z += ww * v.z; acc.w += ww * v.w;
    }
    float* o = out + b * E2 + tid * 4;
    atomicAdd(o + 0, acc.x);
    atomicAdd(o + 1, acc.y);
    atomicAdd(o + 2, acc.z);
    atomicAdd(o + 3, acc.w);
}

// ---------------- launch ----------------
extern "C" void kernel_launch(void* const* d_in, const int* in_sizes, int n_in,
                              void* d_out, int out_size) {
    const float* enc     = (const float*)d_in[0];
    const float* hidden  = (const float*)d_in[1];
    const void*  lengths = d_in[2];
    const float* attn_w  = (const float*)d_in[3];
    const float* attn_b  = (const float*)d_in[4];
    const float* v_w     = (const float*)d_in[5];
    float* out = (float*)d_out;

    k_prep<<<PREP_GRID, 256>>>(hidden, attn_w, attn_b, enc, lengths, out);   // 0

    cudaFuncSetAttribute(k_scores, cudaFuncAttributeMaxDynamicSharedMemorySize, SMEM_TOTAL);
    k_scores<<<dim3(S_ / MTILE, NCHUNKS, B_), 256, SMEM_TOTAL>>>(v_w);       // 1

    k_context<<<dim3(S_ / SCH, B_), 256>>>(enc, out);                        // 2
}